// round 11
// baseline (speedup 1.0000x reference)
#include <cuda_runtime.h>
#include <cstdint>

// IntensityTransformation: out_k[b,c,h,w] = tf_k[b,c, round(255*img[b,c,h,w])]
// B=8, C=3, H=W=1024, LUT=256. Output = concat(out1, out2, out3), fp32.
//
// R11: the R5 body (best so far) with the launch reshaped for 100% occupancy:
// 512-thread blocks, min 4 blocks/SM (= 64 warps/SM, regs capped at 32).
// Evidence from R5/R6/R8/R9: DRAM% is monotone in achieved occupancy and
// nothing else (burst shape, LSU width, smem conflicts) moved it.

static constexpr int PLANES = 24;                    // B*C
static constexpr long long PLANE = 1024LL * 1024LL;  // floats per plane
static constexpr int LUT = 256;

__global__ __launch_bounds__(512, 4)
void intensity_lut_kernel(const float* __restrict__ img,
                          const float* __restrict__ tf1,
                          const float* __restrict__ tf2,
                          const float* __restrict__ tf3,
                          float* __restrict__ out)
{
    __shared__ float s1[LUT];
    __shared__ float s2[LUT];
    __shared__ float s3[LUT];

    const int plane = blockIdx.y;          // 0..23
    const int t = threadIdx.x;             // 0..511

    // Stage this plane's three LUTs into shared memory.
    if (t < LUT) {
        s1[t] = tf1[plane * LUT + t];
        s2[t] = tf2[plane * LUT + t];
        s3[t] = tf3[plane * LUT + t];
    }
    __syncthreads();

    const long long base = (long long)plane * PLANE;
    const float4* __restrict__ in4 = reinterpret_cast<const float4*>(img + base);
    float4* __restrict__ o1 = reinterpret_cast<float4*>(out + base);
    float4* __restrict__ o2 = reinterpret_cast<float4*>(out + (long long)PLANES * PLANE + base);
    float4* __restrict__ o3 = reinterpret_cast<float4*>(out + 2LL * PLANES * PLANE + base);

    const int n4 = (int)(PLANE / 4);       // 262144 float4 per plane
    const int stride = gridDim.x * blockDim.x;

    for (int i = blockIdx.x * blockDim.x + t; i < n4; i += stride) {
        float4 v = in4[i];
        int i0 = __float2int_rn(255.0f * v.x);
        int i1 = __float2int_rn(255.0f * v.y);
        int i2 = __float2int_rn(255.0f * v.z);
        int i3 = __float2int_rn(255.0f * v.w);

        float4 r1 = make_float4(s1[i0], s1[i1], s1[i2], s1[i3]);
        float4 r2 = make_float4(s2[i0], s2[i1], s2[i2], s2[i3]);
        float4 r3 = make_float4(s3[i0], s3[i1], s3[i2], s3[i3]);

        o1[i] = r1;
        o2[i] = r2;
        o3[i] = r3;
    }
}

extern "C" void kernel_launch(void* const* d_in, const int* in_sizes, int n_in,
                              void* d_out, int out_size)
{
    const float* img = (const float*)d_in[0];
    const float* tf1 = (const float*)d_in[1];
    const float* tf2 = (const float*)d_in[2];
    const float* tf3 = (const float*)d_in[3];
    float* out = (float*)d_out;

    // 64 x 24 = 1536 CTAs of 512 threads; 4 CTAs/SM resident = 64 warps/SM.
    // Each thread runs 8 grid-stride iterations.
    dim3 grid(64, PLANES);
    dim3 block(512);
    intensity_lut_kernel<<<grid, block>>>(img, tf1, tf2, tf3, out);
}

// round 13
// speedup vs baseline: 1.0344x; 1.0344x over previous
#include <cuda_runtime.h>
#include <cstdint>

// IntensityTransformation: out_k[b,c,h,w] = tf_k[b,c, round(255*img[b,c,h,w])]
// B=8, C=3, H=W=1024, LUT=256. Output = concat(out1, out2, out3), fp32.
//
// R12: exact R5 body/launch (best: 62.75us kernel), single change:
// __ldcs on the img stream (L1+L2 evict-first) while stores keep default
// policy. Rationale: img is 100MB of read-once data sweeping a 126MB L2;
// with default policy it evicts dirty output lines and fragments the write
// drain. Evict-first reads + normal-resident writes let L2 batch writeback.

static constexpr int PLANES = 24;                    // B*C
static constexpr long long PLANE = 1024LL * 1024LL;  // floats per plane
static constexpr int LUT = 256;

__global__ __launch_bounds__(256)
void intensity_lut_kernel(const float* __restrict__ img,
                          const float* __restrict__ tf1,
                          const float* __restrict__ tf2,
                          const float* __restrict__ tf3,
                          float* __restrict__ out)
{
    __shared__ float s1[LUT];
    __shared__ float s2[LUT];
    __shared__ float s3[LUT];

    const int plane = blockIdx.y;          // 0..23
    const int t = threadIdx.x;             // blockDim.x == 256

    // Stage this plane's three LUTs into shared memory.
    s1[t] = tf1[plane * LUT + t];
    s2[t] = tf2[plane * LUT + t];
    s3[t] = tf3[plane * LUT + t];
    __syncthreads();

    const long long base = (long long)plane * PLANE;
    const float4* __restrict__ in4 = reinterpret_cast<const float4*>(img + base);
    float4* __restrict__ o1 = reinterpret_cast<float4*>(out + base);
    float4* __restrict__ o2 = reinterpret_cast<float4*>(out + (long long)PLANES * PLANE + base);
    float4* __restrict__ o3 = reinterpret_cast<float4*>(out + 2LL * PLANES * PLANE + base);

    const int n4 = (int)(PLANE / 4);       // 262144 float4 per plane
    const int stride = gridDim.x * blockDim.x;

    for (int i = blockIdx.x * blockDim.x + t; i < n4; i += stride) {
        float4 v = __ldcs(&in4[i]);        // evict-first: don't pollute L2
        int i0 = __float2int_rn(255.0f * v.x);
        int i1 = __float2int_rn(255.0f * v.y);
        int i2 = __float2int_rn(255.0f * v.z);
        int i3 = __float2int_rn(255.0f * v.w);

        float4 r1 = make_float4(s1[i0], s1[i1], s1[i2], s1[i3]);
        float4 r2 = make_float4(s2[i0], s2[i1], s2[i2], s2[i3]);
        float4 r3 = make_float4(s3[i0], s3[i1], s3[i2], s3[i3]);

        o1[i] = r1;   // default policy: stay resident, batch the writeback
        o2[i] = r2;
        o3[i] = r3;
    }
}

extern "C" void kernel_launch(void* const* d_in, const int* in_sizes, int n_in,
                              void* d_out, int out_size)
{
    const float* img = (const float*)d_in[0];
    const float* tf1 = (const float*)d_in[1];
    const float* tf2 = (const float*)d_in[2];
    const float* tf3 = (const float*)d_in[3];
    float* out = (float*)d_out;

    dim3 grid(256, PLANES);   // 6144 CTAs, R5's best-performing shape
    dim3 block(256);
    intensity_lut_kernel<<<grid, block>>>(img, tf1, tf2, tf3, out);
}